// round 10
// baseline (speedup 1.0000x reference)
#include <cuda_runtime.h>

#define N_NODES 10000
#define N_EDGES 640000
#define DIM 128
#define CAP 160   // max in-degree bucket capacity (mean 64, sigma 8; 160 ~ 12 sigma)

typedef unsigned long long u64;

// ---------------- scratch (no allocations allowed) ----------------
__device__ int   g_is64;
__device__ int   g_cur [N_NODES];
__device__ int   g_bkt [N_NODES * CAP];
__device__ float g_agg [N_NODES * DIM];
__device__ float g_h1  [N_NODES * DIM];

template <int SEL>
__device__ __forceinline__ const float* sel_ptr(const float* p) {
    if (SEL == 1) return g_agg;
    if (SEL == 2) return g_h1;
    return p;
}

__device__ __forceinline__ int edge_at(const void* ei, int half, int e, int is64) {
    if (is64) {
        return (int)((const long long*)ei)[(size_t)half * N_EDGES + e];
    } else {
        return ((const int*)ei)[(size_t)half * N_EDGES + e];
    }
}

// ---------------- init: zero counters + dtype detect (fused) ----------------
__global__ void k_init(const int* __restrict__ ei32) {
    int i = blockIdx.x * blockDim.x + threadIdx.x;
    if (i < N_NODES) g_cur[i] = 0;
    if (i == 0) {
        int all_zero = 1;
        for (int j = 1; j < 64; j += 2)
            if (ei32[j] != 0) { all_zero = 0; break; }
        g_is64 = all_zero;
    }
}

// ---------------- single-pass bucket scatter ----------------
__global__ void k_scatter(const void* __restrict__ ei) {
    int base = blockIdx.x * (blockDim.x * 4) + threadIdx.x;
    int is64 = g_is64;
#pragma unroll
    for (int j = 0; j < 4; j++) {
        int e = base + j * 256;
        if (e < N_EDGES) {
            int src = edge_at(ei, 0, e, is64);
            int dst = edge_at(ei, 1, e, is64);
            int p = atomicAdd(&g_cur[dst], 1);
            g_bkt[dst * CAP + p] = src;
        }
    }
}

// ---------------- mean aggregation: one warp per destination node ----------------
template <int SRC_SEL>
__global__ void k_agg(const float* __restrict__ hx) {
    int node = (blockIdx.x * blockDim.x + threadIdx.x) >> 5;
    int lane = threadIdx.x & 31;
    if (node >= N_NODES) return;
    const float* h = sel_ptr<SRC_SEL>(hx);
    const int* bkt = &g_bkt[node * CAP];
    int cnt = g_cur[node];
    const float4* h4 = (const float4*)h;
    float4 acc = make_float4(0.f, 0.f, 0.f, 0.f);
    int e = 0;
    for (; e + 4 <= cnt; e += 4) {
        int s0 = bkt[e + 0];
        int s1 = bkt[e + 1];
        int s2 = bkt[e + 2];
        int s3 = bkt[e + 3];
        float4 v0 = __ldg(&h4[s0 * 32 + lane]);
        float4 v1 = __ldg(&h4[s1 * 32 + lane]);
        float4 v2 = __ldg(&h4[s2 * 32 + lane]);
        float4 v3 = __ldg(&h4[s3 * 32 + lane]);
        acc.x += (v0.x + v1.x) + (v2.x + v3.x);
        acc.y += (v0.y + v1.y) + (v2.y + v3.y);
        acc.z += (v0.z + v1.z) + (v2.z + v3.z);
        acc.w += (v0.w + v1.w) + (v2.w + v3.w);
    }
    for (; e < cnt; e++) {
        float4 v = __ldg(&h4[bkt[e] * 32 + lane]);
        acc.x += v.x; acc.y += v.y; acc.z += v.z; acc.w += v.w;
    }
    float inv = 1.0f / (float)(cnt > 0 ? cnt : 1);
    ((float4*)g_agg)[node * 32 + lane] =
        make_float4(acc.x * inv, acc.y * inv, acc.z * inv, acc.w * inv);
}

// ---------------- packed-f32x2 helpers ----------------
__device__ __forceinline__ u64 dup2(float v) {
    u64 r;
    asm("mov.b64 %0, {%1, %1};" : "=l"(r) : "f"(v));
    return r;
}
__device__ __forceinline__ void fma2(u64& acc, u64 a, u64 b) {
    asm("fma.rn.f32x2 %0, %1, %2, %0;" : "+l"(acc) : "l"(a), "l"(b));
}
__device__ __forceinline__ void unpack2(u64 v, float& lo, float& hi) {
    asm("mov.b64 {%0, %1}, %2;" : "=f"(lo), "=f"(hi) : "l"(v));
}

// ---------------- fused multi-matrix GEMM: col-pair f32x2, dup'd A, 16x128 tile --
// out[m,d] = relu( sum_mat( A_mat[m,:] . W_mat[d,:] ) + b0[d] (+ b1[d]) )
// Block: 16 rows x 128 cols, 64 threads (2 warps), grid 625 (10000 = 625*16).
// Warp owns 8 rows; lane owns 4 cols (2 col-pairs).
// A stored DUPLICATED in smem ([a,a] pairs) -> inner-loop broadcast LDS.128 yields
// (a,a) u64s; W col-pairs load directly as u64. ZERO packing movs in inner loop.
// Per (k,mat): ~5 LDS + 16 FMA2.
template <int NMAT, bool NB2, int S0, int S1, int S2, bool OUT_H1>
__global__ __launch_bounds__(64)
void k_gemm(const float* __restrict__ A0, const float* __restrict__ W0,
            const float* __restrict__ A1, const float* __restrict__ W1,
            const float* __restrict__ A2, const float* __restrict__ W2,
            const float* __restrict__ b0, const float* __restrict__ b1,
            float* __restrict__ out_ext) {
    constexpr int BM = 16, BK = 16;
    constexpr int AW = 2 * BM;          // duplicated A row width (32 floats, 128B)
    constexpr int WW = DIM + 4;         // W row width (132 floats)
    __shared__ __align__(16) float As2[NMAT][BK][AW];
    __shared__ __align__(16) float Ws[NMAT][BK][WW];

    const float* Aarr[3];
    Aarr[0] = sel_ptr<S0>(A0);
    if (NMAT > 1) Aarr[1] = sel_ptr<S1>(A1);
    if (NMAT > 2) Aarr[2] = sel_ptr<S2>(A2);
    const float* Warr[3] = {W0, W1, W2};
    float* out = OUT_H1 ? g_h1 : out_ext;

    const int t = threadIdx.x;            // 0..63
    const int m0 = blockIdx.x * BM;
    const int arow = t >> 2;              // 0..15 (A-stage row)
    const int kq = (t & 3) * 4;           // 0,4,8,12
    const int warp = t >> 5;              // 0..1
    const int lane = t & 31;
    const int rowBase = warp * 8;         // warp rows (8)
    const int col = lane * 4;             // lane cols (4 = 2 pairs)

    u64 acc2[8][2];                       // [row][col-pair], packed (col, col+1)
#pragma unroll
    for (int r = 0; r < 8; r++) {
        acc2[r][0] = 0ull;
        acc2[r][1] = 0ull;
    }

    for (int kt = 0; kt < DIM / BK; kt++) {
        const int k0 = kt * BK;
#pragma unroll
        for (int mat = 0; mat < NMAT; mat++) {
            // A tile: 16 rows x BK, stored duplicated. One float4 per thread.
            {
                float4 va = *(const float4*)&Aarr[mat][(m0 + arow) * DIM + k0 + kq];
                *(u64*)&As2[mat][kq + 0][2 * arow] = dup2(va.x);
                *(u64*)&As2[mat][kq + 1][2 * arow] = dup2(va.y);
                *(u64*)&As2[mat][kq + 2][2 * arow] = dup2(va.z);
                *(u64*)&As2[mat][kq + 3][2 * arow] = dup2(va.w);
            }
            // W tile: 128 cols x BK (transposed store). 8 float4 per thread.
#pragma unroll
            for (int i = 0; i < 8; i++) {
                int idx = t + i * 64;               // 0..511
                int d = idx >> 2;                   // 0..127
                int kc = (idx & 3) * 4;             // 0,4,8,12
                float4 vw = *(const float4*)&Warr[mat][d * DIM + k0 + kc];
                Ws[mat][kc + 0][d] = vw.x;
                Ws[mat][kc + 1][d] = vw.y;
                Ws[mat][kc + 2][d] = vw.z;
                Ws[mat][kc + 3][d] = vw.w;
            }
        }
        __syncthreads();
#pragma unroll
        for (int k = 0; k < BK; k++) {
#pragma unroll
            for (int mat = 0; mat < NMAT; mat++) {
                // 8 dup'd A rows: broadcast loads, 16B-aligned (warp*16 floats = 64B)
                const u64* a2 = (const u64*)&As2[mat][k][2 * rowBase];
                // 2 W col-pairs: direct u64 loads (adjacent floats)
                const u64* w2 = (const u64*)&Ws[mat][k][col];
                u64 wp0 = w2[0], wp1 = w2[1];
#pragma unroll
                for (int r = 0; r < 8; r++) {
                    u64 ar = a2[r];
                    fma2(acc2[r][0], ar, wp0);
                    fma2(acc2[r][1], ar, wp1);
                }
            }
        }
        __syncthreads();
    }

    float bb[4];
#pragma unroll
    for (int j = 0; j < 4; j++) {
        bb[j] = b0[col + j];
        if (NB2) bb[j] += b1[col + j];
    }
#pragma unroll
    for (int r = 0; r < 8; r++) {
        float c0, c1, c2, c3;
        unpack2(acc2[r][0], c0, c1);
        unpack2(acc2[r][1], c2, c3);
        int row = m0 + rowBase + r;
        float4 o;
        o.x = fmaxf(c0 + bb[0], 0.f);
        o.y = fmaxf(c1 + bb[1], 0.f);
        o.z = fmaxf(c2 + bb[2], 0.f);
        o.w = fmaxf(c3 + bb[3], 0.f);
        *(float4*)&out[row * DIM + col] = o;
    }
}

// ---------------- launch: kernel launches ONLY, no other CUDA APIs ----------------
extern "C" void kernel_launch(void* const* d_in, const int* in_sizes, int n_in,
                              void* d_out, int out_size) {
    const float* x    = (const float*)d_in[0];
    const void*  ei   = d_in[1];                 // int32 or int64, detected on device
    const float* fc_w = (const float*)d_in[2];
    const float* fc_b = (const float*)d_in[3];
    const float* f_lw = (const float*)d_in[4];
    const float* f_lb = (const float*)d_in[5];
    const float* f_rw = (const float*)d_in[6];
    const float* n_lw = (const float*)d_in[7];
    const float* n_lb = (const float*)d_in[8];
    const float* n_rw = (const float*)d_in[9];
    float* out = (float*)d_out;

    const int TB = 256;
    const int gemm_blocks = N_NODES / 16;        // 625, exact
    const int agg_blocks = (N_NODES * 32 + TB - 1) / TB;
    const int scat_blocks = (N_EDGES + TB * 4 - 1) / (TB * 4);

    // bucket CSR build (single pass, no count/scan)
    k_init<<<(N_NODES + TB - 1) / TB, TB>>>((const int*)ei);
    k_scatter<<<scat_blocks, TB>>>(ei);

    // conv1: g_h1 = relu(mean_agg(x) @ f_lw^T + f_lb + x @ f_rw^T)
    k_agg<0><<<agg_blocks, TB>>>(x);
    k_gemm<2, false, 1, 0, 0, true><<<gemm_blocks, 64>>>(
        nullptr, f_lw, x, f_rw, nullptr, nullptr, f_lb, nullptr, nullptr);

    // conv2 + fc residual, fused:
    // out = relu(mean_agg(g_h1) @ n_lw^T + n_lb + g_h1 @ n_rw^T + x @ fc_w^T + fc_b)
    k_agg<2><<<agg_blocks, TB>>>(nullptr);
    k_gemm<3, true, 1, 2, 0, false><<<gemm_blocks, 64>>>(
        nullptr, n_lw, nullptr, n_rw, x, fc_w, n_lb, fc_b, out);
}

// round 12
// speedup vs baseline: 1.1579x; 1.1579x over previous
#include <cuda_runtime.h>

#define N_NODES 10000
#define N_EDGES 640000
#define DIM 128
#define CAP 160   // max in-degree bucket capacity (mean 64, sigma 8; 160 ~ 12 sigma)

typedef unsigned long long u64;

// ---------------- scratch (no allocations allowed) ----------------
__device__ int   g_is64;
__device__ int   g_cur [N_NODES];
__device__ int   g_bkt [N_NODES * CAP];
__device__ float g_agg [N_NODES * DIM];
__device__ float g_h1  [N_NODES * DIM];

template <int SEL>
__device__ __forceinline__ const float* sel_ptr(const float* p) {
    if (SEL == 1) return g_agg;
    if (SEL == 2) return g_h1;
    return p;
}

__device__ __forceinline__ int edge_at(const void* ei, int half, int e, int is64) {
    if (is64) {
        return (int)((const long long*)ei)[(size_t)half * N_EDGES + e];
    } else {
        return ((const int*)ei)[(size_t)half * N_EDGES + e];
    }
}

// ---------------- init: zero counters + dtype detect (fused) ----------------
__global__ void k_init(const int* __restrict__ ei32) {
    int i = blockIdx.x * blockDim.x + threadIdx.x;
    if (i < N_NODES) g_cur[i] = 0;
    if (i == 0) {
        int all_zero = 1;
        for (int j = 1; j < 64; j += 2)
            if (ei32[j] != 0) { all_zero = 0; break; }
        g_is64 = all_zero;
    }
}

// ---------------- single-pass bucket scatter ----------------
__global__ void k_scatter(const void* __restrict__ ei) {
    int base = blockIdx.x * (blockDim.x * 4) + threadIdx.x;
    int is64 = g_is64;
#pragma unroll
    for (int j = 0; j < 4; j++) {
        int e = base + j * 256;
        if (e < N_EDGES) {
            int src = edge_at(ei, 0, e, is64);
            int dst = edge_at(ei, 1, e, is64);
            int p = atomicAdd(&g_cur[dst], 1);
            g_bkt[dst * CAP + p] = src;
        }
    }
}

// ---------------- mean aggregation: one warp per destination node ----------------
template <int SRC_SEL>
__global__ void k_agg(const float* __restrict__ hx) {
    int node = (blockIdx.x * blockDim.x + threadIdx.x) >> 5;
    int lane = threadIdx.x & 31;
    if (node >= N_NODES) return;
    const float* h = sel_ptr<SRC_SEL>(hx);
    const int* bkt = &g_bkt[node * CAP];
    int cnt = g_cur[node];
    const float4* h4 = (const float4*)h;
    float4 acc = make_float4(0.f, 0.f, 0.f, 0.f);
    int e = 0;
    for (; e + 4 <= cnt; e += 4) {
        int s0 = bkt[e + 0];
        int s1 = bkt[e + 1];
        int s2 = bkt[e + 2];
        int s3 = bkt[e + 3];
        float4 v0 = __ldg(&h4[s0 * 32 + lane]);
        float4 v1 = __ldg(&h4[s1 * 32 + lane]);
        float4 v2 = __ldg(&h4[s2 * 32 + lane]);
        float4 v3 = __ldg(&h4[s3 * 32 + lane]);
        acc.x += (v0.x + v1.x) + (v2.x + v3.x);
        acc.y += (v0.y + v1.y) + (v2.y + v3.y);
        acc.z += (v0.z + v1.z) + (v2.z + v3.z);
        acc.w += (v0.w + v1.w) + (v2.w + v3.w);
    }
    for (; e < cnt; e++) {
        float4 v = __ldg(&h4[bkt[e] * 32 + lane]);
        acc.x += v.x; acc.y += v.y; acc.z += v.z; acc.w += v.w;
    }
    float inv = 1.0f / (float)(cnt > 0 ? cnt : 1);
    ((float4*)g_agg)[node * 32 + lane] =
        make_float4(acc.x * inv, acc.y * inv, acc.z * inv, acc.w * inv);
}

// ---------------- packed-f32x2 helpers ----------------
__device__ __forceinline__ u64 dup2(float v) {
    u64 r;
    asm("mov.b64 %0, {%1, %1};" : "=l"(r) : "f"(v));
    return r;
}
__device__ __forceinline__ void fma2(u64& acc, u64 a, u64 b) {
    asm("fma.rn.f32x2 %0, %1, %2, %0;" : "+l"(acc) : "l"(a), "l"(b));
}
__device__ __forceinline__ void unpack2(u64 v, float& lo, float& hi) {
    asm("mov.b64 {%0, %1}, %2;" : "=f"(lo), "=f"(hi) : "l"(v));
}

// ---------------- fused multi-matrix GEMM (round-9 shape + register prefetch) --
// out[m,d] = relu( sum_mat( A_mat[m,:] . W_mat[d,:] ) + b0[d] (+ b1[d]) )
// BM=32 x BN=64, 128 threads (4 warps), grid 313x2 = 626.
// Warp owns 8 rows (4 packed pairs, broadcast LDS); lane owns 2 cols.
// Tile kt+1 is prefetched into registers BEFORE computing tile kt, so the
// 234-262 cyc L2 latency overlaps the 416-instr compute stage instead of
// serializing at the barrier.
template <int NMAT, bool NB2, int S0, int S1, int S2, bool OUT_H1>
__global__ __launch_bounds__(128)
void k_gemm(const float* __restrict__ A0, const float* __restrict__ W0,
            const float* __restrict__ A1, const float* __restrict__ W1,
            const float* __restrict__ A2, const float* __restrict__ W2,
            const float* __restrict__ b0, const float* __restrict__ b1,
            float* __restrict__ out_ext) {
    constexpr int BM = 32, BN = 64, BK = 16;
    __shared__ __align__(16) float As[NMAT][BK][BM + 4];
    __shared__ __align__(16) float Ws[NMAT][BK][BN + 4];

    const float* Aarr[3];
    Aarr[0] = sel_ptr<S0>(A0);
    if (NMAT > 1) Aarr[1] = sel_ptr<S1>(A1);
    if (NMAT > 2) Aarr[2] = sel_ptr<S2>(A2);
    const float* Warr[3] = {W0, W1, W2};
    float* out = OUT_H1 ? g_h1 : out_ext;

    const int t = threadIdx.x;            // 0..127
    const int m0 = blockIdx.x * BM;
    const int n0 = blockIdx.y * BN;
    const int q  = t >> 2;                // 0..31
    const int kq = (t & 3) * 4;           // 0,4,8,12
    const int warp = t >> 5;              // 0..3
    const int lane = t & 31;
    const int rowBase = warp * 8;         // warp rows (8)
    const int col = lane * 2;             // lane cols (2), local to tile

    float4 pa[NMAT], pw0[NMAT], pw1[NMAT];

    // prefetch tile kt=0
    {
        const int grow = m0 + q;
#pragma unroll
        for (int mat = 0; mat < NMAT; mat++) {
            pa[mat] = make_float4(0.f, 0.f, 0.f, 0.f);
            if (grow < N_NODES)
                pa[mat] = *(const float4*)&Aarr[mat][grow * DIM + kq];
            pw0[mat] = *(const float4*)&Warr[mat][(n0 + q) * DIM + kq];
            pw1[mat] = *(const float4*)&Warr[mat][(n0 + q + 32) * DIM + kq];
        }
    }

    u64 acc2[4][2];                       // [row-pair][col]
#pragma unroll
    for (int p = 0; p < 4; p++)
#pragma unroll
        for (int j = 0; j < 2; j++) acc2[p][j] = 0ull;

    for (int kt = 0; kt < DIM / BK; kt++) {
        // store prefetched tile to smem
#pragma unroll
        for (int mat = 0; mat < NMAT; mat++) {
            As[mat][kq + 0][q] = pa[mat].x;
            As[mat][kq + 1][q] = pa[mat].y;
            As[mat][kq + 2][q] = pa[mat].z;
            As[mat][kq + 3][q] = pa[mat].w;
            Ws[mat][kq + 0][q] = pw0[mat].x;
            Ws[mat][kq + 1][q] = pw0[mat].y;
            Ws[mat][kq + 2][q] = pw0[mat].z;
            Ws[mat][kq + 3][q] = pw0[mat].w;
            Ws[mat][kq + 0][q + 32] = pw1[mat].x;
            Ws[mat][kq + 1][q + 32] = pw1[mat].y;
            Ws[mat][kq + 2][q + 32] = pw1[mat].z;
            Ws[mat][kq + 3][q + 32] = pw1[mat].w;
        }
        __syncthreads();

        // issue LDGs for tile kt+1 now; latency hides under compute below
        if (kt < DIM / BK - 1) {
            const int k0 = (kt + 1) * BK;
            const int grow = m0 + q;
#pragma unroll
            for (int mat = 0; mat < NMAT; mat++) {
                pa[mat] = make_float4(0.f, 0.f, 0.f, 0.f);
                if (grow < N_NODES)
                    pa[mat] = *(const float4*)&Aarr[mat][grow * DIM + k0 + kq];
                pw0[mat] = *(const float4*)&Warr[mat][(n0 + q) * DIM + k0 + kq];
                pw1[mat] = *(const float4*)&Warr[mat][(n0 + q + 32) * DIM + k0 + kq];
            }
        }

        // compute on current smem tile
#pragma unroll
        for (int k = 0; k < BK; k++) {
#pragma unroll
            for (int mat = 0; mat < NMAT; mat++) {
                const u64* a64 = (const u64*)&As[mat][k][rowBase];
                u64 ap0 = a64[0], ap1 = a64[1], ap2 = a64[2], ap3 = a64[3];
                float2 wv = *(const float2*)&Ws[mat][k][col];
                u64 wd0 = dup2(wv.x), wd1 = dup2(wv.y);
                fma2(acc2[0][0], ap0, wd0);
                fma2(acc2[1][0], ap1, wd0);
                fma2(acc2[2][0], ap2, wd0);
                fma2(acc2[3][0], ap3, wd0);
                fma2(acc2[0][1], ap0, wd1);
                fma2(acc2[1][1], ap1, wd1);
                fma2(acc2[2][1], ap2, wd1);
                fma2(acc2[3][1], ap3, wd1);
            }
        }
        __syncthreads();
    }

    float bb[2];
#pragma unroll
    for (int j = 0; j < 2; j++) {
        bb[j] = b0[n0 + col + j];
        if (NB2) bb[j] += b1[n0 + col + j];
    }
#pragma unroll
    for (int p = 0; p < 4; p++) {
        float lo0, hi0, lo1, hi1;
        unpack2(acc2[p][0], lo0, hi0);
        unpack2(acc2[p][1], lo1, hi1);
        int r0 = m0 + rowBase + 2 * p;
        int r1 = r0 + 1;
        if (r0 < N_NODES) {
            float2 o;
            o.x = fmaxf(lo0 + bb[0], 0.f);
            o.y = fmaxf(lo1 + bb[1], 0.f);
            *(float2*)&out[r0 * DIM + n0 + col] = o;
        }
        if (r1 < N_NODES) {
            float2 o;
            o.x = fmaxf(hi0 + bb[0], 0.f);
            o.y = fmaxf(hi1 + bb[1], 0.f);
            *(float2*)&out[r1 * DIM + n0 + col] = o;
        }
    }
}

// ---------------- launch: kernel launches ONLY, no other CUDA APIs ----------------
extern "C" void kernel_launch(void* const* d_in, const int* in_sizes, int n_in,
                              void* d_out, int out_size) {
    const float* x    = (const float*)d_in[0];
    const void*  ei   = d_in[1];                 // int32 or int64, detected on device
    const float* fc_w = (const float*)d_in[2];
    const float* fc_b = (const float*)d_in[3];
    const float* f_lw = (const float*)d_in[4];
    const float* f_lb = (const float*)d_in[5];
    const float* f_rw = (const float*)d_in[6];
    const float* n_lw = (const float*)d_in[7];
    const float* n_lb = (const float*)d_in[8];
    const float* n_rw = (const float*)d_in[9];
    float* out = (float*)d_out;

    const int TB = 256;
    const dim3 gemm_grid((N_NODES + 31) / 32, 2);
    const int agg_blocks = (N_NODES * 32 + TB - 1) / TB;
    const int scat_blocks = (N_EDGES + TB * 4 - 1) / (TB * 4);

    // bucket CSR build (single pass, no count/scan)
    k_init<<<(N_NODES + TB - 1) / TB, TB>>>((const int*)ei);
    k_scatter<<<scat_blocks, TB>>>(ei);

    // conv1: g_h1 = relu(mean_agg(x) @ f_lw^T + f_lb + x @ f_rw^T)
    k_agg<0><<<agg_blocks, TB>>>(x);
    k_gemm<2, false, 1, 0, 0, true><<<gemm_grid, 128>>>(
        nullptr, f_lw, x, f_rw, nullptr, nullptr, f_lb, nullptr, nullptr);

    // conv2 + fc residual, fused:
    // out = relu(mean_agg(g_h1) @ n_lw^T + n_lb + g_h1 @ n_rw^T + x @ fc_w^T + fc_b)
    k_agg<2><<<agg_blocks, TB>>>(nullptr);
    k_gemm<3, true, 1, 2, 0, false><<<gemm_grid, 128>>>(
        nullptr, n_lw, nullptr, n_rw, x, fc_w, n_lb, fc_b, out);
}

// round 13
// speedup vs baseline: 1.2203x; 1.0539x over previous
#include <cuda_runtime.h>
#include <cuda_fp16.h>

#define N_NODES 10000
#define N_EDGES 640000
#define DIM 128
#define CAP 160   // max in-degree bucket capacity (mean 64, sigma 8; 160 ~ 12 sigma)

typedef unsigned long long u64;

// ---------------- scratch (no allocations allowed) ----------------
__device__ int     g_is64;
__device__ int     g_cur [N_NODES];
__device__ int     g_bkt [N_NODES * CAP];
__device__ float   g_agg [N_NODES * DIM];
__device__ float   g_h1  [N_NODES * DIM];
__device__ __half2 g_xh  [N_NODES * DIM / 2];   // fp16 copy of x (gather table)
__device__ __half2 g_h1h [N_NODES * DIM / 2];   // fp16 copy of h1 (gather table)

template <int SEL>
__device__ __forceinline__ const float* sel_ptr(const float* p) {
    if (SEL == 1) return g_agg;
    if (SEL == 2) return g_h1;
    return p;
}

__device__ __forceinline__ int edge_at(const void* ei, int half, int e, int is64) {
    if (is64) {
        return (int)((const long long*)ei)[(size_t)half * N_EDGES + e];
    } else {
        return ((const int*)ei)[(size_t)half * N_EDGES + e];
    }
}

// ---------------- init: zero counters + dtype detect (fused) ----------------
__global__ void k_init(const int* __restrict__ ei32) {
    int i = blockIdx.x * blockDim.x + threadIdx.x;
    if (i < N_NODES) g_cur[i] = 0;
    if (i == 0) {
        int all_zero = 1;
        for (int j = 1; j < 64; j += 2)
            if (ei32[j] != 0) { all_zero = 0; break; }
        g_is64 = all_zero;
    }
}

// ---------------- x -> fp16 gather table ----------------
__global__ void k_tohalf(const float* __restrict__ x) {
    int i = blockIdx.x * blockDim.x + threadIdx.x;   // one half2 per thread
    if (i < N_NODES * DIM / 2) {
        float2 v = ((const float2*)x)[i];
        g_xh[i] = __float22half2_rn(v);
    }
}

// ---------------- single-pass bucket scatter ----------------
__global__ void k_scatter(const void* __restrict__ ei) {
    int base = blockIdx.x * (blockDim.x * 4) + threadIdx.x;
    int is64 = g_is64;
#pragma unroll
    for (int j = 0; j < 4; j++) {
        int e = base + j * 256;
        if (e < N_EDGES) {
            int src = edge_at(ei, 0, e, is64);
            int dst = edge_at(ei, 1, e, is64);
            int p = atomicAdd(&g_cur[dst], 1);
            g_bkt[dst * CAP + p] = src;
        }
    }
}

// ---------------- mean aggregation (fp16 gather, fp32 accumulate) --------------
// SRC: 0 = g_xh, 1 = g_h1h. One warp per node; lane owns 4 features (2 half2).
template <int SRC>
__global__ void k_agg_h() {
    int node = (blockIdx.x * blockDim.x + threadIdx.x) >> 5;
    int lane = threadIdx.x & 31;
    if (node >= N_NODES) return;
    const __half2* h2 = (SRC == 0) ? g_xh : g_h1h;
    const int* bkt = &g_bkt[node * CAP];
    int cnt = g_cur[node];
    float2 acc0 = make_float2(0.f, 0.f);
    float2 acc1 = make_float2(0.f, 0.f);
    int e = 0;
    for (; e + 4 <= cnt; e += 4) {
        int s0 = bkt[e + 0];
        int s1 = bkt[e + 1];
        int s2 = bkt[e + 2];
        int s3 = bkt[e + 3];
        // 8B per lane per row: 2 half2 = features 4*lane .. 4*lane+3
        uint2 r0 = __ldg((const uint2*)&h2[s0 * (DIM / 2) + lane * 2]);
        uint2 r1 = __ldg((const uint2*)&h2[s1 * (DIM / 2) + lane * 2]);
        uint2 r2 = __ldg((const uint2*)&h2[s2 * (DIM / 2) + lane * 2]);
        uint2 r3 = __ldg((const uint2*)&h2[s3 * (DIM / 2) + lane * 2]);
        float2 a0 = __half22float2(*(const __half2*)&r0.x);
        float2 b0 = __half22float2(*(const __half2*)&r0.y);
        float2 a1 = __half22float2(*(const __half2*)&r1.x);
        float2 b1 = __half22float2(*(const __half2*)&r1.y);
        float2 a2 = __half22float2(*(const __half2*)&r2.x);
        float2 b2 = __half22float2(*(const __half2*)&r2.y);
        float2 a3 = __half22float2(*(const __half2*)&r3.x);
        float2 b3 = __half22float2(*(const __half2*)&r3.y);
        acc0.x += (a0.x + a1.x) + (a2.x + a3.x);
        acc0.y += (a0.y + a1.y) + (a2.y + a3.y);
        acc1.x += (b0.x + b1.x) + (b2.x + b3.x);
        acc1.y += (b0.y + b1.y) + (b2.y + b3.y);
    }
    for (; e < cnt; e++) {
        uint2 r = __ldg((const uint2*)&h2[bkt[e] * (DIM / 2) + lane * 2]);
        float2 a = __half22float2(*(const __half2*)&r.x);
        float2 b = __half22float2(*(const __half2*)&r.y);
        acc0.x += a.x; acc0.y += a.y;
        acc1.x += b.x; acc1.y += b.y;
    }
    float inv = 1.0f / (float)(cnt > 0 ? cnt : 1);
    ((float4*)g_agg)[node * 32 + lane] =
        make_float4(acc0.x * inv, acc0.y * inv, acc1.x * inv, acc1.y * inv);
}

// ---------------- packed-f32x2 helpers ----------------
__device__ __forceinline__ u64 dup2(float v) {
    u64 r;
    asm("mov.b64 %0, {%1, %1};" : "=l"(r) : "f"(v));
    return r;
}
__device__ __forceinline__ void fma2(u64& acc, u64 a, u64 b) {
    asm("fma.rn.f32x2 %0, %1, %2, %0;" : "+l"(acc) : "l"(a), "l"(b));
}
__device__ __forceinline__ void unpack2(u64 v, float& lo, float& hi) {
    asm("mov.b64 {%0, %1}, %2;" : "=f"(lo), "=f"(hi) : "l"(v));
}

// ---------------- fused multi-matrix GEMM (round-12 best: prefetch + f32x2) ----
// out[m,d] = relu( sum_mat( A_mat[m,:] . W_mat[d,:] ) + b0[d] (+ b1[d]) )
// BM=32 x BN=64, 128 threads (4 warps), grid 313x2 = 626.
// OUT_H1: dual-write fp32 g_h1 and fp16 g_h1h (gather table for conv2).
template <int NMAT, bool NB2, int S0, int S1, int S2, bool OUT_H1>
__global__ __launch_bounds__(128)
void k_gemm(const float* __restrict__ A0, const float* __restrict__ W0,
            const float* __restrict__ A1, const float* __restrict__ W1,
            const float* __restrict__ A2, const float* __restrict__ W2,
            const float* __restrict__ b0, const float* __restrict__ b1,
            float* __restrict__ out_ext) {
    constexpr int BM = 32, BN = 64, BK = 16;
    __shared__ __align__(16) float As[NMAT][BK][BM + 4];
    __shared__ __align__(16) float Ws[NMAT][BK][BN + 4];

    const float* Aarr[3];
    Aarr[0] = sel_ptr<S0>(A0);
    if (NMAT > 1) Aarr[1] = sel_ptr<S1>(A1);
    if (NMAT > 2) Aarr[2] = sel_ptr<S2>(A2);
    const float* Warr[3] = {W0, W1, W2};
    float* out = OUT_H1 ? g_h1 : out_ext;

    const int t = threadIdx.x;            // 0..127
    const int m0 = blockIdx.x * BM;
    const int n0 = blockIdx.y * BN;
    const int q  = t >> 2;                // 0..31
    const int kq = (t & 3) * 4;           // 0,4,8,12
    const int warp = t >> 5;              // 0..3
    const int lane = t & 31;
    const int rowBase = warp * 8;         // warp rows (8)
    const int col = lane * 2;             // lane cols (2), local to tile

    float4 pa[NMAT], pw0[NMAT], pw1[NMAT];

    // prefetch tile kt=0
    {
        const int grow = m0 + q;
#pragma unroll
        for (int mat = 0; mat < NMAT; mat++) {
            pa[mat] = make_float4(0.f, 0.f, 0.f, 0.f);
            if (grow < N_NODES)
                pa[mat] = *(const float4*)&Aarr[mat][grow * DIM + kq];
            pw0[mat] = *(const float4*)&Warr[mat][(n0 + q) * DIM + kq];
            pw1[mat] = *(const float4*)&Warr[mat][(n0 + q + 32) * DIM + kq];
        }
    }

    u64 acc2[4][2];                       // [row-pair][col]
#pragma unroll
    for (int p = 0; p < 4; p++)
#pragma unroll
        for (int j = 0; j < 2; j++) acc2[p][j] = 0ull;

    for (int kt = 0; kt < DIM / BK; kt++) {
        // store prefetched tile to smem
#pragma unroll
        for (int mat = 0; mat < NMAT; mat++) {
            As[mat][kq + 0][q] = pa[mat].x;
            As[mat][kq + 1][q] = pa[mat].y;
            As[mat][kq + 2][q] = pa[mat].z;
            As[mat][kq + 3][q] = pa[mat].w;
            Ws[mat][kq + 0][q] = pw0[mat].x;
            Ws[mat][kq + 1][q] = pw0[mat].y;
            Ws[mat][kq + 2][q] = pw0[mat].z;
            Ws[mat][kq + 3][q] = pw0[mat].w;
            Ws[mat][kq + 0][q + 32] = pw1[mat].x;
            Ws[mat][kq + 1][q + 32] = pw1[mat].y;
            Ws[mat][kq + 2][q + 32] = pw1[mat].z;
            Ws[mat][kq + 3][q + 32] = pw1[mat].w;
        }
        __syncthreads();

        // issue LDGs for tile kt+1 now; latency hides under compute below
        if (kt < DIM / BK - 1) {
            const int k0 = (kt + 1) * BK;
            const int grow = m0 + q;
#pragma unroll
            for (int mat = 0; mat < NMAT; mat++) {
                pa[mat] = make_float4(0.f, 0.f, 0.f, 0.f);
                if (grow < N_NODES)
                    pa[mat] = *(const float4*)&Aarr[mat][grow * DIM + k0 + kq];
                pw0[mat] = *(const float4*)&Warr[mat][(n0 + q) * DIM + k0 + kq];
                pw1[mat] = *(const float4*)&Warr[mat][(n0 + q + 32) * DIM + k0 + kq];
            }
        }

        // compute on current smem tile
#pragma unroll
        for (int k = 0; k < BK; k++) {
#pragma unroll
            for (int mat = 0; mat < NMAT; mat++) {
                const u64* a64 = (const u64*)&As[mat][k][rowBase];
                u64 ap0 = a64[0], ap1 = a64[1], ap2 = a64[2], ap3 = a64[3];
                float2 wv = *(const float2*)&Ws[mat][k][col];
                u64 wd0 = dup2(wv.x), wd1 = dup2(wv.y);
                fma2(acc2[0][0], ap0, wd0);
                fma2(acc2[1][0], ap1, wd0);
                fma2(acc2[2][0], ap2, wd0);
                fma2(acc2[3][0], ap3, wd0);
                fma2(acc2[0][1], ap0, wd1);
                fma2(acc2[1][1], ap1, wd1);
                fma2(acc2[2][1], ap2, wd1);
                fma2(acc2[3][1], ap3, wd1);
            }
        }
        __syncthreads();
    }

    float bb[2];
#pragma unroll
    for (int j = 0; j < 2; j++) {
        bb[j] = b0[n0 + col + j];
        if (NB2) bb[j] += b1[n0 + col + j];
    }
#pragma unroll
    for (int p = 0; p < 4; p++) {
        float lo0, hi0, lo1, hi1;
        unpack2(acc2[p][0], lo0, hi0);
        unpack2(acc2[p][1], lo1, hi1);
        int r0 = m0 + rowBase + 2 * p;
        int r1 = r0 + 1;
        if (r0 < N_NODES) {
            float2 o;
            o.x = fmaxf(lo0 + bb[0], 0.f);
            o.y = fmaxf(lo1 + bb[1], 0.f);
            *(float2*)&out[r0 * DIM + n0 + col] = o;
            if (OUT_H1)
                g_h1h[(r0 * DIM + n0 + col) / 2] = __float22half2_rn(o);
        }
        if (r1 < N_NODES) {
            float2 o;
            o.x = fmaxf(hi0 + bb[0], 0.f);
            o.y = fmaxf(hi1 + bb[1], 0.f);
            *(float2*)&out[r1 * DIM + n0 + col] = o;
            if (OUT_H1)
                g_h1h[(r1 * DIM + n0 + col) / 2] = __float22half2_rn(o);
        }
    }
}

// ---------------- launch: kernel launches ONLY, no other CUDA APIs ----------------
extern "C" void kernel_launch(void* const* d_in, const int* in_sizes, int n_in,
                              void* d_out, int out_size) {
    const float* x    = (const float*)d_in[0];
    const void*  ei   = d_in[1];                 // int32 or int64, detected on device
    const float* fc_w = (const float*)d_in[2];
    const float* fc_b = (const float*)d_in[3];
    const float* f_lw = (const float*)d_in[4];
    const float* f_lb = (const float*)d_in[5];
    const float* f_rw = (const float*)d_in[6];
    const float* n_lw = (const float*)d_in[7];
    const float* n_lb = (const float*)d_in[8];
    const float* n_rw = (const float*)d_in[9];
    float* out = (float*)d_out;

    const int TB = 256;
    const dim3 gemm_grid((N_NODES + 31) / 32, 2);
    const int agg_blocks = (N_NODES * 32 + TB - 1) / TB;
    const int scat_blocks = (N_EDGES + TB * 4 - 1) / (TB * 4);
    const int half_blocks = (N_NODES * DIM / 2 + TB - 1) / TB;

    // bucket CSR build (single pass) + fp16 x table
    k_init<<<(N_NODES + TB - 1) / TB, TB>>>((const int*)ei);
    k_scatter<<<scat_blocks, TB>>>(ei);
    k_tohalf<<<half_blocks, TB>>>(x);

    // conv1: g_h1 = relu(mean_agg(x) @ f_lw^T + f_lb + x @ f_rw^T)  [+ fp16 copy]
    k_agg_h<0><<<agg_blocks, TB>>>();
    k_gemm<2, false, 1, 0, 0, true><<<gemm_grid, 128>>>(
        nullptr, f_lw, x, f_rw, nullptr, nullptr, f_lb, nullptr, nullptr);

    // conv2 + fc residual, fused:
    // out = relu(mean_agg(h1) @ n_lw^T + n_lb + h1 @ n_rw^T + x @ fc_w^T + fc_b)
    k_agg_h<1><<<agg_blocks, TB>>>();
    k_gemm<3, true, 1, 2, 0, false><<<gemm_grid, 128>>>(
        nullptr, n_lw, nullptr, n_rw, x, fc_w, n_lb, fc_b, out);
}

// round 15
// speedup vs baseline: 1.9146x; 1.5690x over previous
#include <cuda_runtime.h>
#include <cuda_fp16.h>
#include <cstdint>

#define N_NODES 10000
#define N_EDGES 640000
#define DIM 128
#define CAP 160   // max in-degree bucket capacity (mean 64, sigma 8; 160 ~ 12 sigma)

// ---------------- scratch (no allocations allowed) ----------------
__device__ int     g_is64;
__device__ int     g_cur [N_NODES];
__device__ int     g_bkt [N_NODES * CAP];
__device__ __half2 g_xh  [N_NODES * DIM / 2];   // fp16 x (gather + GEMM A table)
__device__ __half2 g_h1h [N_NODES * DIM / 2];   // fp16 h1
__device__ __half2 g_aggh[N_NODES * DIM / 2];   // fp16 mean-agg output
__device__ __half  g_wh  [5 * DIM * DIM];       // fp16 weights: f_lw,f_rw,n_lw,n_rw,fc_w

__device__ __forceinline__ int edge_at(const void* ei, int half, int e, int is64) {
    if (is64) {
        return (int)((const long long*)ei)[(size_t)half * N_EDGES + e];
    } else {
        return ((const int*)ei)[(size_t)half * N_EDGES + e];
    }
}

__device__ __forceinline__ uint32_t smem_u32(const void* p) {
    uint32_t a;
    asm("{ .reg .u64 t; cvta.to.shared.u64 t, %1; cvt.u32.u64 %0, t; }"
        : "=r"(a) : "l"(p));
    return a;
}

__device__ __forceinline__ void ldsm_x4(uint32_t& r0, uint32_t& r1,
                                        uint32_t& r2, uint32_t& r3, uint32_t addr) {
    asm volatile("ldmatrix.sync.aligned.m8n8.x4.shared.b16 {%0,%1,%2,%3}, [%4];"
                 : "=r"(r0), "=r"(r1), "=r"(r2), "=r"(r3) : "r"(addr));
}

__device__ __forceinline__ void mma_16816(float* c, const uint32_t* a,
                                          const uint32_t* b) {
    asm volatile(
        "mma.sync.aligned.m16n8k16.row.col.f32.f16.f16.f32 "
        "{%0,%1,%2,%3}, {%4,%5,%6,%7}, {%8,%9}, {%0,%1,%2,%3};"
        : "+f"(c[0]), "+f"(c[1]), "+f"(c[2]), "+f"(c[3])
        : "r"(a[0]), "r"(a[1]), "r"(a[2]), "r"(a[3]), "r"(b[0]), "r"(b[1]));
}

// ---------------- init: zero counters + dtype detect ----------------
__global__ void k_init(const int* __restrict__ ei32) {
    int i = blockIdx.x * blockDim.x + threadIdx.x;
    if (i < N_NODES) g_cur[i] = 0;
    if (i == 0) {
        int all_zero = 1;
        for (int j = 1; j < 64; j += 2)
            if (ei32[j] != 0) { all_zero = 0; break; }
        g_is64 = all_zero;
    }
}

// ---------------- x -> fp16 table ----------------
__global__ void k_tohalf(const float* __restrict__ x) {
    int i = blockIdx.x * blockDim.x + threadIdx.x;
    if (i < N_NODES * DIM / 2) {
        float2 v = ((const float2*)x)[i];
        g_xh[i] = __float22half2_rn(v);
    }
}

// ---------------- weights -> fp16 (f_lw, f_rw, n_lw, n_rw, fc_w) ----------------
__global__ void k_wh(const float* __restrict__ f_lw, const float* __restrict__ f_rw,
                     const float* __restrict__ n_lw, const float* __restrict__ n_rw,
                     const float* __restrict__ fc_w) {
    int i = blockIdx.x * blockDim.x + threadIdx.x;
    if (i < 5 * DIM * DIM) {
        int sel = i >> 14, rem = i & 16383;
        const float* p = (sel == 0) ? f_lw : (sel == 1) ? f_rw
                       : (sel == 2) ? n_lw : (sel == 3) ? n_rw : fc_w;
        g_wh[i] = __float2half_rn(p[rem]);
    }
}

// ---------------- single-pass bucket scatter ----------------
__global__ void k_scatter(const void* __restrict__ ei) {
    int base = blockIdx.x * (blockDim.x * 4) + threadIdx.x;
    int is64 = g_is64;
#pragma unroll
    for (int j = 0; j < 4; j++) {
        int e = base + j * 256;
        if (e < N_EDGES) {
            int src = edge_at(ei, 0, e, is64);
            int dst = edge_at(ei, 1, e, is64);
            int p = atomicAdd(&g_cur[dst], 1);
            g_bkt[dst * CAP + p] = src;
        }
    }
}

// ---------------- mean aggregation (fp16 gather, fp32 accumulate, fp16 out) ----
// SRC: 0 = g_xh, 1 = g_h1h. One warp per node; lane owns 4 features (2 half2).
template <int SRC>
__global__ void k_agg_h() {
    int node = (blockIdx.x * blockDim.x + threadIdx.x) >> 5;
    int lane = threadIdx.x & 31;
    if (node >= N_NODES) return;
    const __half2* h2 = (SRC == 0) ? g_xh : g_h1h;
    const int* bkt = &g_bkt[node * CAP];
    int cnt = g_cur[node];
    float2 acc0 = make_float2(0.f, 0.f);
    float2 acc1 = make_float2(0.f, 0.f);
    int e = 0;
    for (; e + 4 <= cnt; e += 4) {
        int s0 = bkt[e + 0];
        int s1 = bkt[e + 1];
        int s2 = bkt[e + 2];
        int s3 = bkt[e + 3];
        uint2 r0 = __ldg((const uint2*)&h2[s0 * (DIM / 2) + lane * 2]);
        uint2 r1 = __ldg((const uint2*)&h2[s1 * (DIM / 2) + lane * 2]);
        uint2 r2 = __ldg((const uint2*)&h2[s2 * (DIM / 2) + lane * 2]);
        uint2 r3 = __ldg((const uint2*)&h2[s3 * (DIM / 2) + lane * 2]);
        float2 a0 = __half22float2(*(const __half2*)&r0.x);
        float2 b0 = __half22float2(*(const __half2*)&r0.y);
        float2 a1 = __half22float2(*(const __half2*)&r1.x);
        float2 b1 = __half22float2(*(const __half2*)&r1.y);
        float2 a2 = __half22float2(*(const __half2*)&r2.x);
        float2 b2 = __half22float2(*(const __half2*)&r2.y);
        float2 a3 = __half22float2(*(const __half2*)&r3.x);
        float2 b3 = __half22float2(*(const __half2*)&r3.y);
        acc0.x += (a0.x + a1.x) + (a2.x + a3.x);
        acc0.y += (a0.y + a1.y) + (a2.y + a3.y);
        acc1.x += (b0.x + b1.x) + (b2.x + b3.x);
        acc1.y += (b0.y + b1.y) + (b2.y + b3.y);
    }
    for (; e < cnt; e++) {
        uint2 r = __ldg((const uint2*)&h2[bkt[e] * (DIM / 2) + lane * 2]);
        float2 a = __half22float2(*(const __half2*)&r.x);
        float2 b = __half22float2(*(const __half2*)&r.y);
        acc0.x += a.x; acc0.y += a.y;
        acc1.x += b.x; acc1.y += b.y;
    }
    float inv = 1.0f / (float)(cnt > 0 ? cnt : 1);
    __half2 h0 = __float22half2_rn(make_float2(acc0.x * inv, acc0.y * inv));
    __half2 h1v = __float22half2_rn(make_float2(acc1.x * inv, acc1.y * inv));
    uint2 o;
    o.x = *(uint32_t*)&h0;
    o.y = *(uint32_t*)&h1v;
    *(uint2*)&g_aggh[node * (DIM / 2) + lane * 2] = o;
}

// ---------------- tensor-core fused GEMM (fp16 mma.sync, f32 accum) ------------
// out[m,d] = relu( sum_mat( A_mat[m,:] . W_mat[d,:] ) + b0[d] (+ b1[d]) )
// Block: 64 rows x 128 cols, 256 threads (8 warps = 2 row x 4 col).
// Warp tile 32x32 = 2 m16-tiles x 4 n8-tiles. K-chunks of 32 halves in smem,
// stride 40 halves (80B: 16B-aligned, ldmatrix conflict-free).
// A sources: S* in {0:g_aggh, 1:g_xh, 2:g_h1h}; weights by index into g_wh.
// OUT_H1: write fp16 g_h1h; else write fp32 out_ext.
template <int NMAT, bool NB2, int S0, int S1, int S2, int W0I, int W1I, int W2I,
          bool OUT_H1>
__global__ __launch_bounds__(256)
void k_gemm_mma(const float* __restrict__ b0, const float* __restrict__ b1,
                float* __restrict__ out_ext) {
    constexpr int BM = 64, CH = 32, STR = 40;   // chunk halves, smem stride
    __shared__ __align__(16) __half As[NMAT][BM][STR];
    __shared__ __align__(16) __half Wsm[NMAT][DIM][STR];

    const __half* Asrc[3];
    {
        const __half* tbl[3] = {(const __half*)g_aggh, (const __half*)g_xh,
                                (const __half*)g_h1h};
        Asrc[0] = tbl[S0];
        if (NMAT > 1) Asrc[1] = tbl[S1];
        if (NMAT > 2) Asrc[2] = tbl[S2];
    }
    const int widx[3] = {W0I, W1I, W2I};

    const int t = threadIdx.x;
    const int m0 = blockIdx.x * BM;
    const int warp = t >> 5;
    const int lane = t & 31;
    const int warp_row = warp >> 2;       // 0..1 -> rows warp_row*32
    const int warp_col = warp & 3;        // 0..3 -> cols warp_col*32

    // ldmatrix per-lane offsets (halves) within a [row][STR] tile
    const int a_row = (lane & 7) + ((lane >> 3) & 1) * 8;
    const int a_k   = (lane >> 4) * 8;
    const int b_row = (lane & 7) + (lane >> 4) * 8;
    const int b_k   = ((lane >> 3) & 1) * 8;

    const uint32_t baseA = smem_u32(&As[0][0][0]);
    const uint32_t baseW = smem_u32(&Wsm[0][0][0]);

    float c[2][4][4];
#pragma unroll
    for (int mi = 0; mi < 2; mi++)
#pragma unroll
        for (int ni = 0; ni < 4; ni++)
#pragma unroll
            for (int r = 0; r < 4; r++) c[mi][ni][r] = 0.f;

    for (int kt = 0; kt < DIM / CH; kt++) {
        const int k0 = kt * CH;
        // stage A: BM rows x CH halves per mat (uint4 = 8 halves per thread)
        {
            int row = t >> 2;             // 0..63
            int seg = (t & 3) * 8;        // 0,8,16,24
            int grow = m0 + row;
#pragma unroll
            for (int mat = 0; mat < NMAT; mat++) {
                uint4 v = make_uint4(0, 0, 0, 0);
                if (grow < N_NODES)
                    v = *(const uint4*)&Asrc[mat][grow * DIM + k0 + seg];
                *(uint4*)&As[mat][row][seg] = v;
            }
        }
        // stage W: DIM rows x CH halves per mat (2 uint4 per thread)
#pragma unroll
        for (int r2 = 0; r2 < 2; r2++) {
            int idx = t + r2 * 256;       // 0..511
            int row = idx >> 2;           // 0..127
            int seg = (idx & 3) * 8;
#pragma unroll
            for (int mat = 0; mat < NMAT; mat++) {
                uint4 v = *(const uint4*)&g_wh[widx[mat] * DIM * DIM + row * DIM + k0 + seg];
                *(uint4*)&Wsm[mat][row][seg] = v;
            }
        }
        __syncthreads();

#pragma unroll
        for (int ks = 0; ks < 2; ks++) {
            const int kofs = ks * 16;
#pragma unroll
            for (int mat = 0; mat < NMAT; mat++) {
                uint32_t a[2][4];
#pragma unroll
                for (int mi = 0; mi < 2; mi++) {
                    uint32_t addr = baseA +
                        (((mat * BM) + warp_row * 32 + mi * 16 + a_row) * STR
                         + kofs + a_k) * 2;
                    ldsm_x4(a[mi][0], a[mi][1], a[mi][2], a[mi][3], addr);
                }
                uint32_t b[4][2];
#pragma unroll
                for (int nj = 0; nj < 2; nj++) {
                    uint32_t addr = baseW +
                        (((mat * DIM) + warp_col * 32 + nj * 16 + b_row) * STR
                         + kofs + b_k) * 2;
                    uint32_t q0, q1, q2, q3;
                    ldsm_x4(q0, q1, q2, q3, addr);
                    b[nj * 2 + 0][0] = q0; b[nj * 2 + 0][1] = q1;
                    b[nj * 2 + 1][0] = q2; b[nj * 2 + 1][1] = q3;
                }
#pragma unroll
                for (int mi = 0; mi < 2; mi++)
#pragma unroll
                    for (int ni = 0; ni < 4; ni++)
                        mma_16816(c[mi][ni], a[mi], b[ni]);
            }
        }
        __syncthreads();
    }

    // epilogue: c[mi][ni]: rows m0+warp_row*32+mi*16+{lane/4, +8}, cols
    // warp_col*32+ni*8+(lane%4)*2 (+1)
    const int colq = (lane & 3) * 2;
    const int rowq = lane >> 2;
#pragma unroll
    for (int mi = 0; mi < 2; mi++) {
#pragma unroll
        for (int ni = 0; ni < 4; ni++) {
            int colb = warp_col * 32 + ni * 8 + colq;
            float bb0 = b0[colb], bb1 = b0[colb + 1];
            if (NB2) { bb0 += b1[colb]; bb1 += b1[colb + 1]; }
#pragma unroll
            for (int h = 0; h < 2; h++) {
                int row = m0 + warp_row * 32 + mi * 16 + rowq + h * 8;
                if (row < N_NODES) {
                    float o0 = fmaxf(c[mi][ni][h * 2 + 0] + bb0, 0.f);
                    float o1 = fmaxf(c[mi][ni][h * 2 + 1] + bb1, 0.f);
                    if (OUT_H1) {
                        __half2 hv = __float22half2_rn(make_float2(o0, o1));
                        g_h1h[(row * DIM + colb) / 2] = hv;
                    } else {
                        *(float2*)&out_ext[row * DIM + colb] = make_float2(o0, o1);
                    }
                }
            }
        }
    }
}

// ---------------- launch: kernel launches ONLY, no other CUDA APIs ----------------
extern "C" void kernel_launch(void* const* d_in, const int* in_sizes, int n_in,
                              void* d_out, int out_size) {
    const float* x    = (const float*)d_in[0];
    const void*  ei   = d_in[1];                 // int32 or int64, detected on device
    const float* fc_w = (const float*)d_in[2];
    const float* fc_b = (const float*)d_in[3];
    const float* f_lw = (const float*)d_in[4];
    const float* f_lb = (const float*)d_in[5];
    const float* f_rw = (const float*)d_in[6];
    const float* n_lw = (const float*)d_in[7];
    const float* n_lb = (const float*)d_in[8];
    const float* n_rw = (const float*)d_in[9];
    float* out = (float*)d_out;

    const int TB = 256;
    const int gemm_blocks = (N_NODES + 63) / 64;        // 157
    const int agg_blocks = (N_NODES * 32 + TB - 1) / TB;
    const int scat_blocks = (N_EDGES + TB * 4 - 1) / (TB * 4);
    const int half_blocks = (N_NODES * DIM / 2 + TB - 1) / TB;
    const int wh_blocks = (5 * DIM * DIM + TB - 1) / TB;

    // CSR bucket build + fp16 tables
    k_init<<<(N_NODES + TB - 1) / TB, TB>>>((const int*)ei);
    k_scatter<<<scat_blocks, TB>>>(ei);
    k_tohalf<<<half_blocks, TB>>>(x);
    k_wh<<<wh_blocks, TB>>>(f_lw, f_rw, n_lw, n_rw, fc_w);

    // conv1: h1 = relu(mean_agg(x) @ f_lw^T + f_lb + x @ f_rw^T)   [fp16 out]
    k_agg_h<0><<<agg_blocks, TB>>>();
    k_gemm_mma<2, false, 0, 1, 0, 0, 1, 0, true><<<gemm_blocks, 256>>>(
        f_lb, nullptr, nullptr);

    // conv2 + fc residual:
    // out = relu(mean_agg(h1) @ n_lw^T + n_lb + h1 @ n_rw^T + x @ fc_w^T + fc_b)
    k_agg_h<1><<<agg_blocks, TB>>>();
    k_gemm_mma<3, true, 0, 2, 1, 2, 3, 4, false><<<gemm_blocks, 256>>>(
        n_lb, fc_b, out);
}